// round 3
// baseline (speedup 1.0000x reference)
#include <cuda_runtime.h>
#include <math.h>

#define IN_DIM   128
#define OUT_DIM  64
#define REL_DIM  32
#define NEG_SLOPE 0.01f
#define MAX_N 50000
#define MAX_E 800000
#define SCAN_CHUNK 512
#define NEG_BIG (-1e30f)

// ---------------- scratch (device globals; no allocation allowed) ----------
__device__ float g_z[MAX_N * OUT_DIM];       // 12.8 MB
__device__ float g_s1[MAX_N];
__device__ float g_s2[MAX_N];
__device__ float g_logit[MAX_E];
__device__ int   g_counts[MAX_N + 1];
__device__ int   g_cursor[MAX_N];
__device__ int   g_rowptr[MAX_N + 1];
__device__ int   g_partial[256];
__device__ int   g_eidx[MAX_E];
__device__ float g_consts[40];               // [0..31]=b3, [32]=c4, [33]=c5

// ---------------- init: zero counters + fold small projections -------------
__global__ void k_init(const float* __restrict__ W_r, const float* __restrict__ W_s,
                       const float* __restrict__ W_t, const float* __restrict__ a, int N) {
    int i = blockIdx.x * blockDim.x + threadIdx.x;
    if (i <= N) g_counts[i] = 0;
    if (i < N)  g_cursor[i] = 0;
    if (blockIdx.x == 0) {
        int t = threadIdx.x;
        if (t < REL_DIM) {            // b3 = W_r @ a3
            float s = 0.f;
            #pragma unroll
            for (int d = 0; d < OUT_DIM; d++) s += W_r[t * OUT_DIM + d] * a[2 * OUT_DIM + d];
            g_consts[t] = s;
        } else if (t == 32) {         // c4 = W_s . a4
            float s = 0.f;
            for (int d = 0; d < OUT_DIM; d++) s += W_s[d] * a[3 * OUT_DIM + d];
            g_consts[32] = s;
        } else if (t == 33) {         // c5 = W_t . a5
            float s = 0.f;
            for (int d = 0; d < OUT_DIM; d++) s += W_t[d] * a[4 * OUT_DIM + d];
            g_consts[33] = s;
        }
    }
}

// ---------------- K1: z = h @ W_n, plus s1 = z.a1, s2 = z.a2 ---------------
// 256 threads, 256 rows/block. Thread (cg=warp 0..7, rg=lane 0..31) computes
// an 8x8 register tile: rows {rg+32i}, cols {cg*8+j}. k-chunked by 32.
__global__ __launch_bounds__(256) void k_gemm(const float* __restrict__ h,
                                              const float* __restrict__ Wn,
                                              const float* __restrict__ a, int N) {
    __shared__ float hsm[32][256];   // [k][row] — lane-consecutive rows: conflict-free
    __shared__ float wsm[32][64];
    __shared__ float s1s[256], s2s[256];

    int tid = threadIdx.x;
    int cg = tid >> 5, rg = tid & 31;
    int base = blockIdx.x * 256;

    float acc[8][8];
    #pragma unroll
    for (int i = 0; i < 8; i++)
        #pragma unroll
        for (int j = 0; j < 8; j++) acc[i][j] = 0.f;

    for (int kc = 0; kc < 4; kc++) {
        // load h chunk [256 rows][32 k], transposed into hsm[k][row]
        int row = base + tid;
        #pragma unroll
        for (int q = 0; q < 8; q++) {
            float4 v = make_float4(0.f, 0.f, 0.f, 0.f);
            if (row < N) v = *(const float4*)(h + (size_t)row * IN_DIM + kc * 32 + 4 * q);
            hsm[4 * q + 0][tid] = v.x;
            hsm[4 * q + 1][tid] = v.y;
            hsm[4 * q + 2][tid] = v.z;
            hsm[4 * q + 3][tid] = v.w;
        }
        // load W chunk [32 k][64 c]
        #pragma unroll
        for (int q = 0; q < 8; q++) {
            int idx = tid * 8 + q;
            int k = idx >> 6, c = idx & 63;
            wsm[k][c] = Wn[(kc * 32 + k) * OUT_DIM + c];
        }
        __syncthreads();

        #pragma unroll
        for (int kk = 0; kk < 32; kk++) {
            float wv[8], hv[8];
            #pragma unroll
            for (int j = 0; j < 8; j++) wv[j] = wsm[kk][cg * 8 + j];
            #pragma unroll
            for (int i = 0; i < 8; i++) hv[i] = hsm[kk][rg + 32 * i];
            #pragma unroll
            for (int i = 0; i < 8; i++)
                #pragma unroll
                for (int j = 0; j < 8; j++) acc[i][j] += hv[i] * wv[j];
        }
        __syncthreads();
    }

    // epilogue: s1/s2 partials + z stores
    s1s[tid] = 0.f; s2s[tid] = 0.f;
    __syncthreads();

    float a1v[8], a2v[8];
    #pragma unroll
    for (int j = 0; j < 8; j++) { a1v[j] = a[cg * 8 + j]; a2v[j] = a[OUT_DIM + cg * 8 + j]; }

    #pragma unroll
    for (int i = 0; i < 8; i++) {
        float p1 = 0.f, p2 = 0.f;
        #pragma unroll
        for (int j = 0; j < 8; j++) { p1 += acc[i][j] * a1v[j]; p2 += acc[i][j] * a2v[j]; }
        atomicAdd(&s1s[rg + 32 * i], p1);
        atomicAdd(&s2s[rg + 32 * i], p2);
        int row = base + rg + 32 * i;
        if (row < N) {
            float4 o0 = make_float4(acc[i][0], acc[i][1], acc[i][2], acc[i][3]);
            float4 o1 = make_float4(acc[i][4], acc[i][5], acc[i][6], acc[i][7]);
            *(float4*)(g_z + (size_t)row * OUT_DIM + cg * 8)     = o0;
            *(float4*)(g_z + (size_t)row * OUT_DIM + cg * 8 + 4) = o1;
        }
    }
    __syncthreads();
    int row = base + tid;
    if (row < N) { g_s1[row] = s1s[tid]; g_s2[row] = s2s[tid]; }
}

// ---------------- K2: edge logits + leaky relu + dst histogram -------------
__global__ __launch_bounds__(256) void k_logit(const float* __restrict__ relation,
                                               const float* __restrict__ score,
                                               const float* __restrict__ ts,
                                               const int* __restrict__ src,
                                               const int* __restrict__ dst, int E) {
    __shared__ float b3[REL_DIM];
    __shared__ float c45[2];
    if (threadIdx.x < REL_DIM) b3[threadIdx.x] = g_consts[threadIdx.x];
    if (threadIdx.x == 32) { c45[0] = g_consts[32]; c45[1] = g_consts[33]; }
    __syncthreads();

    int e = blockIdx.x * 256 + threadIdx.x;
    if (e >= E) return;

    const float4* rp = (const float4*)(relation + (size_t)e * REL_DIM);
    float dotr = 0.f;
    #pragma unroll
    for (int q = 0; q < 8; q++) {
        float4 r = rp[q];
        dotr += r.x * b3[4 * q] + r.y * b3[4 * q + 1] + r.z * b3[4 * q + 2] + r.w * b3[4 * q + 3];
    }
    int s = __ldg(src + e), d = __ldg(dst + e);
    float lo = g_s1[s] + g_s2[d] + dotr + score[e] * c45[0] + ts[e] * c45[1];
    lo = (lo >= 0.f) ? lo : NEG_SLOPE * lo;
    g_logit[e] = lo;
    atomicAdd(&g_counts[d], 1);
}

// ---------------- exclusive scan of counts -> rowptr (3 kernels) -----------
__global__ void k_scan1(int N) {
    __shared__ int sm[SCAN_CHUNK];
    int idx = blockIdx.x * SCAN_CHUNK + threadIdx.x;
    sm[threadIdx.x] = (idx < N) ? g_counts[idx] : 0;
    __syncthreads();
    for (int off = SCAN_CHUNK / 2; off > 0; off >>= 1) {
        if (threadIdx.x < off) sm[threadIdx.x] += sm[threadIdx.x + off];
        __syncthreads();
    }
    if (threadIdx.x == 0) g_partial[blockIdx.x] = sm[0];
}
__global__ void k_scan2(int NB, int N) {
    if (threadIdx.x == 0) {
        int run = 0;
        for (int b = 0; b < NB; b++) { int t = g_partial[b]; g_partial[b] = run; run += t; }
        g_rowptr[N] = run;
    }
}
__global__ void k_scan3(int N) {
    __shared__ int sm[SCAN_CHUNK];
    int t = threadIdx.x;
    int idx = blockIdx.x * SCAN_CHUNK + t;
    int v = (idx < N) ? g_counts[idx] : 0;
    sm[t] = v;
    __syncthreads();
    for (int off = 1; off < SCAN_CHUNK; off <<= 1) {
        int x = (t >= off) ? sm[t - off] : 0;
        __syncthreads();
        sm[t] += x;
        __syncthreads();
    }
    if (idx < N) g_rowptr[idx] = g_partial[blockIdx.x] + sm[t] - v;
}

// ---------------- scatter edges into dst buckets ---------------------------
__global__ void k_scatter(const int* __restrict__ dst, int E) {
    int e = blockIdx.x * 256 + threadIdx.x;
    if (e >= E) return;
    int d = __ldg(dst + e);
    int p = g_rowptr[d] + atomicAdd(&g_cursor[d], 1);
    g_eidx[p] = e;
}

// ---------------- K4: warp-per-node online softmax + aggregation -----------
// NOTE: m is initialized to a large FINITE negative (not -inf) so that the
// butterfly merge of two empty lanes computes exp(0)=1 scaling a zero sum,
// instead of exp(-inf - -inf) = exp(NaN).
__global__ __launch_bounds__(256) void k_agg(const int* __restrict__ src,
                                             float* __restrict__ out, int N) {
    int warp = (blockIdx.x * blockDim.x + threadIdx.x) >> 5;
    int lane = threadIdx.x & 31;
    if (warp >= N) return;
    int start = g_rowptr[warp];
    int cnt   = g_rowptr[warp + 1] - start;

    // online softmax statistics across this node's edges
    float m = NEG_BIG, ssum = 0.f;
    for (int i = lane; i < cnt; i += 32) {
        int e = g_eidx[start + i];
        float l = g_logit[e];
        float nm = fmaxf(m, l);
        ssum = ssum * __expf(m - nm) + __expf(l - nm);
        m = nm;
    }
    #pragma unroll
    for (int off = 16; off; off >>= 1) {
        float om = __shfl_xor_sync(0xffffffffu, m, off);
        float os = __shfl_xor_sync(0xffffffffu, ssum, off);
        float nm = fmaxf(m, om);
        ssum = ssum * __expf(m - nm) + os * __expf(om - nm);
        m = nm;
    }
    float inv = (ssum > 0.f) ? 1.f / ssum : 0.f;

    float2 acc = make_float2(0.f, 0.f);
    for (int base = 0; base < cnt; base += 32) {
        int i = base + lane;
        float w = 0.f; int s = 0;
        if (i < cnt) {
            int e = g_eidx[start + i];
            w = __expf(g_logit[e] - m) * inv;
            s = __ldg(src + e);
        }
        int lim = min(32, cnt - base);
        for (int j = 0; j < lim; j++) {
            int   sj = __shfl_sync(0xffffffffu, s, j);
            float wj = __shfl_sync(0xffffffffu, w, j);
            float2 zv = *(const float2*)(g_z + (size_t)sj * OUT_DIM + lane * 2);
            acc.x += wj * zv.x;
            acc.y += wj * zv.y;
        }
    }
    *(float2*)(out + (size_t)warp * OUT_DIM + lane * 2) = acc;
}

// ---------------- launch -----------------------------------------------------
// input order (metadata): h, relation, score, timestamp, src, dst, W_n, W_r, W_s, W_t, a
extern "C" void kernel_launch(void* const* d_in, const int* in_sizes, int n_in,
                              void* d_out, int out_size) {
    const float* h        = (const float*)d_in[0];
    const float* relation = (const float*)d_in[1];
    const float* score    = (const float*)d_in[2];
    const float* ts       = (const float*)d_in[3];
    const int*   src      = (const int*)d_in[4];
    const int*   dst      = (const int*)d_in[5];
    const float* W_n      = (const float*)d_in[6];
    const float* W_r      = (const float*)d_in[7];
    const float* W_s      = (const float*)d_in[8];
    const float* W_t      = (const float*)d_in[9];
    const float* a        = (const float*)d_in[10];
    float* out = (float*)d_out;

    int N = in_sizes[0] / IN_DIM;
    int E = in_sizes[4];
    int NB = (N + SCAN_CHUNK - 1) / SCAN_CHUNK;

    k_init   <<<(N + 256) / 256, 256>>>(W_r, W_s, W_t, a, N);
    k_gemm   <<<(N + 255) / 256, 256>>>(h, W_n, a, N);
    k_logit  <<<(E + 255) / 256, 256>>>(relation, score, ts, src, dst, E);
    k_scan1  <<<NB, SCAN_CHUNK>>>(N);
    k_scan2  <<<1, 32>>>(NB, N);
    k_scan3  <<<NB, SCAN_CHUNK>>>(N);
    k_scatter<<<(E + 255) / 256, 256>>>(dst, E);
    k_agg    <<<(N * 32 + 255) / 256, 256>>>(src, out, N);
}